// round 9
// baseline (speedup 1.0000x reference)
#include <cuda_runtime.h>
#include <cstdint>

#define CCH 128
#define KK3 27
#define SA 136                         // padded smem row stride in floats
#define SMEM_DYN (2 * 128 * SA * 4)    // A tile + B tile = 139264 bytes

__device__ float g_sum[CCH];
__device__ float g_sqs[CCH];

static __device__ __forceinline__ float to_tf32(float x) {
    float r; asm("cvt.rna.tf32.f32 %0, %1;" : "=f"(r) : "f"(x)); return r;
}

static __device__ __forceinline__ void mma8(float* c, const uint32_t* a,
                                            uint32_t b0, uint32_t b1) {
    asm volatile(
        "mma.sync.aligned.m16n8k8.row.col.f32.tf32.tf32.f32 "
        "{%0,%1,%2,%3}, {%4,%5,%6,%7}, {%8,%9}, {%0,%1,%2,%3};"
        : "+f"(c[0]), "+f"(c[1]), "+f"(c[2]), "+f"(c[3])
        : "r"(a[0]), "r"(a[1]), "r"(a[2]), "r"(a[3]), "r"(b0), "r"(b1));
}

// ---------------------------------------------------------------------------
// Conv: persistent CTAs over flattened (k, m_tile). Per tile:
//   gather A[128x128] -> smem ; mma.sync tf32 (warp 4x2 layout) ;
//   C frags -> smem (reuse A buffer) ; red.global.add.v4 scatter.
// B = W[k] [K=128 x N=128] stays resident in smem for a whole k segment.
// ---------------------------------------------------------------------------
__global__ void __launch_bounds__(256, 1)
conv_kernel(const float* __restrict__ feats, const float* __restrict__ Wmat,
            const int* __restrict__ in_maps, const int* __restrict__ out_maps,
            float* __restrict__ out, int Mtot) {
    extern __shared__ float sm[];
    float* const As = sm;               // 128 x SA
    float* const Bs = sm + 128 * SA;    // 128 x SA  (Bs[k][n] = W[k][k_idx][n])

    const int tid  = threadIdx.x;
    const int wid  = tid >> 5;
    const int lane = tid & 31;
    const int gid  = lane >> 2;        // 0..7
    const int tg   = lane & 3;         // 0..3
    const int warp_m = wid & 3;        // 0..3  (32-row block)
    const int warp_n = wid >> 2;       // 0..1  (64-col block)

    const int TPK   = (Mtot + 127) >> 7;
    const int total = KK3 * TPK;
    const int chunk = (total + gridDim.x - 1) / gridDim.x;
    int t = blockIdx.x * chunk;
    const int t1 = min(total, t + chunk);

    while (t < t1) {
        const int kk     = t / TPK;
        const int segEnd = min(t1, (kk + 1) * TPK);
        const int kt0    = kk * TPK;
        const int* imk   = in_maps  + (size_t)kk * Mtot;
        const int* omk   = out_maps + (size_t)kk * Mtot;
        const float4* Wk4 = reinterpret_cast<const float4*>(Wmat + (size_t)kk * (CCH * CCH));

        // Load B (no transpose needed: fragment mapping consumes [k][n]).
#pragma unroll
        for (int p = 0; p < 16; ++p) {
            int lin4 = (p << 8) + tid;           // 0..4095 float4s
            int row  = lin4 >> 5;                // k index
            int n4   = lin4 & 31;
            float4 v = __ldg(Wk4 + lin4);
            v.x = to_tf32(v.x); v.y = to_tf32(v.y);
            v.z = to_tf32(v.z); v.w = to_tf32(v.w);
            *reinterpret_cast<float4*>(&Bs[row * SA + (n4 << 2)]) = v;
        }

        for (int j = t; j < segEnd; ++j) {
            const int tb = (j - kt0) << 7;
            __syncthreads();   // B ready / previous scatter done reading As

            // Gather A tile (OOB rows -> zero), values rounded to tf32.
#pragma unroll
            for (int p = 0; p < 16; ++p) {
                int lin = (p << 8) + tid;
                int row = lin >> 5, q = lin & 31;
                int gm  = tb + row;
                float4 v = make_float4(0.f, 0.f, 0.f, 0.f);
                if (gm < Mtot) {
                    int g = __ldg(imk + gm);
                    v = __ldg(reinterpret_cast<const float4*>(feats) + ((size_t)g << 5) + q);
                    v.x = to_tf32(v.x); v.y = to_tf32(v.y);
                    v.z = to_tf32(v.z); v.w = to_tf32(v.w);
                }
                *reinterpret_cast<float4*>(&As[row * SA + (q << 2)]) = v;
            }
            __syncthreads();

            // MMA: each warp computes a 32x64 sub-tile = 2(M) x 8(N) frags, K=16 steps.
            float acc[2][8][4];
#pragma unroll
            for (int mt = 0; mt < 2; ++mt)
#pragma unroll
                for (int nt = 0; nt < 8; ++nt)
#pragma unroll
                    for (int e = 0; e < 4; ++e) acc[mt][nt][e] = 0.f;

#pragma unroll 4
            for (int ks = 0; ks < 16; ++ks) {
                const int kb = ks << 3;
                uint32_t a[2][4];
#pragma unroll
                for (int mt = 0; mt < 2; ++mt) {
                    const int r = (warp_m << 5) + (mt << 4) + gid;
                    a[mt][0] = __float_as_uint(As[r * SA + kb + tg]);
                    a[mt][1] = __float_as_uint(As[(r + 8) * SA + kb + tg]);
                    a[mt][2] = __float_as_uint(As[r * SA + kb + tg + 4]);
                    a[mt][3] = __float_as_uint(As[(r + 8) * SA + kb + tg + 4]);
                }
#pragma unroll
                for (int nt = 0; nt < 8; ++nt) {
                    const int cn = (warp_n << 6) + (nt << 3) + gid;
                    uint32_t b0 = __float_as_uint(Bs[(kb + tg) * SA + cn]);
                    uint32_t b1 = __float_as_uint(Bs[(kb + tg + 4) * SA + cn]);
                    mma8(acc[0][nt], a[0], b0, b1);
                    mma8(acc[1][nt], a[1], b0, b1);
                }
            }
            __syncthreads();   // all warps done reading As

            // C fragments -> As (c0,c1 and c2,c3 are row-adjacent pairs).
#pragma unroll
            for (int mt = 0; mt < 2; ++mt)
#pragma unroll
                for (int nt = 0; nt < 8; ++nt) {
                    const int r = (warp_m << 5) + (mt << 4) + gid;
                    const int c = (warp_n << 6) + (nt << 3) + (tg << 1);
                    *reinterpret_cast<float2*>(&As[r * SA + c]) =
                        make_float2(acc[mt][nt][0], acc[mt][nt][1]);
                    *reinterpret_cast<float2*>(&As[(r + 8) * SA + c]) =
                        make_float2(acc[mt][nt][2], acc[mt][nt][3]);
                }
            __syncthreads();

            // Scatter: warp w -> row (w&3)*32+lane, cols (w>>2)*64..+63.
            {
                const int r  = ((wid & 3) << 5) + lane;
                const int cb = (wid >> 2) << 6;
                const int gm = tb + r;
                if (gm < Mtot) {
                    float* optr = out + (size_t)__ldg(omk + gm) * CCH + cb;
                    const float* crow = &As[r * SA + cb];
#pragma unroll
                    for (int q = 0; q < 16; ++q) {
                        float4 v = *reinterpret_cast<const float4*>(crow + (q << 2));
                        asm volatile("red.global.add.v4.f32 [%0], {%1,%2,%3,%4};" ::
                                     "l"(optr + (q << 2)),
                                     "f"(v.x), "f"(v.y), "f"(v.z), "f"(v.w) : "memory");
                    }
                }
            }
        }
        t = segEnd;
    }
}

__global__ void __launch_bounds__(256) zero_kernel(float4* __restrict__ o, int n4) {
    int i = blockIdx.x * blockDim.x + threadIdx.x;
    if (blockIdx.x == 0 && threadIdx.x < CCH) { g_sum[threadIdx.x] = 0.f; g_sqs[threadIdx.x] = 0.f; }
    for (; i < n4; i += gridDim.x * blockDim.x)
        o[i] = make_float4(0.f, 0.f, 0.f, 0.f);
}

__global__ void __launch_bounds__(256) stats_kernel(const float4* __restrict__ out4, int Nrows) {
    __shared__ float4 ss[256], sq[256];
    const int tid = threadIdx.x, c4 = tid & 31, rl = tid >> 5;
    float4 s = make_float4(0.f, 0.f, 0.f, 0.f), q = s;
    for (int r = blockIdx.x * 8 + rl; r < Nrows; r += gridDim.x * 8) {
        float4 v = __ldg(out4 + (size_t)r * 32 + c4);
        s.x += v.x; s.y += v.y; s.z += v.z; s.w += v.w;
        q.x += v.x * v.x; q.y += v.y * v.y; q.z += v.z * v.z; q.w += v.w * v.w;
    }
    ss[tid] = s; sq[tid] = q;
    __syncthreads();
    if (rl == 0) {
#pragma unroll
        for (int j = 1; j < 8; ++j) {
            float4 a = ss[c4 + (j << 5)], b = sq[c4 + (j << 5)];
            s.x += a.x; s.y += a.y; s.z += a.z; s.w += a.w;
            q.x += b.x; q.y += b.y; q.z += b.z; q.w += b.w;
        }
        const int c = c4 << 2;
        atomicAdd(&g_sum[c + 0], s.x); atomicAdd(&g_sum[c + 1], s.y);
        atomicAdd(&g_sum[c + 2], s.z); atomicAdd(&g_sum[c + 3], s.w);
        atomicAdd(&g_sqs[c + 0], q.x); atomicAdd(&g_sqs[c + 1], q.y);
        atomicAdd(&g_sqs[c + 2], q.z); atomicAdd(&g_sqs[c + 3], q.w);
    }
}

__global__ void __launch_bounds__(256) norm_kernel(float4* __restrict__ out4,
                                                   const float* __restrict__ gamma,
                                                   const float* __restrict__ beta, int Nrows) {
    const int tid = threadIdx.x, c4 = tid & 31, rl = tid >> 5;
    const float invN = 1.0f / (float)Nrows;
    const int c = c4 << 2;
    float4 A, B;
    {
        float m0 = g_sum[c + 0] * invN, m1 = g_sum[c + 1] * invN;
        float m2 = g_sum[c + 2] * invN, m3 = g_sum[c + 3] * invN;
        A.x = rsqrtf(fmaxf(g_sqs[c + 0] * invN - m0 * m0, 0.f) + 1e-5f) * __ldg(gamma + c + 0);
        A.y = rsqrtf(fmaxf(g_sqs[c + 1] * invN - m1 * m1, 0.f) + 1e-5f) * __ldg(gamma + c + 1);
        A.z = rsqrtf(fmaxf(g_sqs[c + 2] * invN - m2 * m2, 0.f) + 1e-5f) * __ldg(gamma + c + 2);
        A.w = rsqrtf(fmaxf(g_sqs[c + 3] * invN - m3 * m3, 0.f) + 1e-5f) * __ldg(gamma + c + 3);
        B.x = __ldg(beta + c + 0) - m0 * A.x;
        B.y = __ldg(beta + c + 1) - m1 * A.y;
        B.z = __ldg(beta + c + 2) - m2 * A.z;
        B.w = __ldg(beta + c + 3) - m3 * A.w;
    }
    for (int r = blockIdx.x * 8 + rl; r < Nrows; r += gridDim.x * 8) {
        const size_t idx = (size_t)r * 32 + c4;
        float4 v = out4[idx];
        v.x = fmaf(v.x, A.x, B.x); v.y = fmaf(v.y, A.y, B.y);
        v.z = fmaf(v.z, A.z, B.z); v.w = fmaf(v.w, A.w, B.w);
        out4[idx] = v;
    }
}

extern "C" void kernel_launch(void* const* d_in, const int* in_sizes, int n_in,
                              void* d_out, int out_size) {
    const float* feats    = (const float*)d_in[0];
    const float* Wmat     = (const float*)d_in[1];
    const float* gamma    = (const float*)d_in[2];
    const float* beta     = (const float*)d_in[3];
    const int*   in_maps  = (const int*)d_in[4];
    const int*   out_maps = (const int*)d_in[5];
    float* out = (float*)d_out;

    const int Mtot  = in_sizes[4] / KK3;
    const int Nrows = out_size / CCH;

    cudaFuncSetAttribute(conv_kernel, cudaFuncAttributeMaxDynamicSharedMemorySize, SMEM_DYN);

    zero_kernel<<<2048, 256>>>((float4*)out, Nrows * (CCH / 4));
    conv_kernel<<<152, 256, SMEM_DYN>>>(feats, Wmat, in_maps, out_maps, out, Mtot);
    stats_kernel<<<1024, 256>>>((const float4*)out, Nrows);
    norm_kernel<<<1024, 256>>>((float4*)out, gamma, beta, Nrows);
}

// round 11
// speedup vs baseline: 1.6060x; 1.6060x over previous
#include <cuda_runtime.h>
#include <cstdint>

#define CCH 128
#define KK3 27
#define SAF 132                         // A/bounce smem row stride (floats)
#define SBF 136                         // B smem row stride (floats)
#define A_BYTES (128 * SAF * 4)         // 67584
#define B_BYTES (128 * SBF * 4)         // 69632
#define SMEM_DYN (2 * A_BYTES + B_BYTES) // 204800

__device__ float g_sum[CCH];
__device__ float g_sqs[CCH];

static __device__ __forceinline__ float to_tf32(float x) {
    float r; asm("cvt.rna.tf32.f32 %0, %1;" : "=f"(r) : "f"(x)); return r;
}

static __device__ __forceinline__ void mma8(float* c, const uint32_t* a,
                                            uint32_t b0, uint32_t b1) {
    asm volatile(
        "mma.sync.aligned.m16n8k8.row.col.f32.tf32.tf32.f32 "
        "{%0,%1,%2,%3}, {%4,%5,%6,%7}, {%8,%9}, {%0,%1,%2,%3};"
        : "+f"(c[0]), "+f"(c[1]), "+f"(c[2]), "+f"(c[3])
        : "r"(a[0]), "r"(a[1]), "r"(a[2]), "r"(a[3]), "r"(b0), "r"(b1));
}

// Gather 128x128 f32 tile into A smem (stride SAF). OOB rows -> 0. tf32-rounded.
static __device__ __forceinline__ void gather_tile(float* __restrict__ As,
                                                   const float* __restrict__ feats,
                                                   const int* __restrict__ imk,
                                                   int tb, int Mtot, int tid) {
#pragma unroll
    for (int p = 0; p < 8; ++p) {
        int lin = (p << 9) + tid;          // 0..4095 float4 slots
        int row = lin >> 5, q = lin & 31;
        int gm  = tb + row;
        float4 v = make_float4(0.f, 0.f, 0.f, 0.f);
        if (gm < Mtot) {
            int g = __ldg(imk + gm);
            v = __ldg(reinterpret_cast<const float4*>(feats) + ((size_t)g << 5) + q);
            v.x = to_tf32(v.x); v.y = to_tf32(v.y);
            v.z = to_tf32(v.z); v.w = to_tf32(v.w);
        }
        *reinterpret_cast<float4*>(&As[row * SAF + (q << 2)]) = v;
    }
}

// ---------------------------------------------------------------------------
// Persistent conv: per tile  [gather(next) || mma(cur)] -> bounce C -> red.v4
// 512 threads, 16 warps in 4(m) x 4(n) grid, 32x32 warp tiles, A double-buffered.
// ---------------------------------------------------------------------------
__global__ void __launch_bounds__(512, 1)
conv_kernel(const float* __restrict__ feats, const float* __restrict__ Wmat,
            const int* __restrict__ in_maps, const int* __restrict__ out_maps,
            float* __restrict__ out, int Mtot) {
    extern __shared__ float sm[];
    float* const A0 = sm;                       // 128 x SAF
    float* const A1 = sm + 128 * SAF;           // 128 x SAF
    float* const Bs = sm + 2 * 128 * SAF;       // 128 x SBF  (Bs[k][n])

    const int tid  = threadIdx.x;
    const int wid  = tid >> 5;
    const int lane = tid & 31;
    const int gid  = lane >> 2;      // 0..7
    const int tg   = lane & 3;       // 0..3
    const int warp_m = wid & 3;      // 32-row block
    const int warp_n = wid >> 2;     // 32-col block

    const int TPK   = (Mtot + 127) >> 7;
    const int total = KK3 * TPK;
    const int chunk = (total + gridDim.x - 1) / gridDim.x;
    int t = blockIdx.x * chunk;
    const int t1 = min(total, t + chunk);

    while (t < t1) {
        const int kk     = t / TPK;
        const int segEnd = min(t1, (kk + 1) * TPK);
        const int kt0    = kk * TPK;
        const int* imk   = in_maps  + (size_t)kk * Mtot;
        const int* omk   = out_maps + (size_t)kk * Mtot;
        const float4* Wk4 = reinterpret_cast<const float4*>(Wmat + (size_t)kk * (CCH * CCH));

        // Load B = W[k] as [k][n], stride SBF (conflict-free fragment reads).
#pragma unroll
        for (int p = 0; p < 8; ++p) {
            int lin4 = (p << 9) + tid;
            int row  = lin4 >> 5, n4 = lin4 & 31;
            float4 v = __ldg(Wk4 + lin4);
            v.x = to_tf32(v.x); v.y = to_tf32(v.y);
            v.z = to_tf32(v.z); v.w = to_tf32(v.w);
            *reinterpret_cast<float4*>(&Bs[row * SBF + (n4 << 2)]) = v;
        }
        // Prologue gather for first tile of segment into A0.
        gather_tile(A0, feats, imk, (t - kt0) << 7, Mtot, tid);
        __syncthreads();

        int cur = 0;
        for (int j = t; j < segEnd; ++j) {
            const int tb = (j - kt0) << 7;
            float* const Ac = cur ? A1 : A0;
            float* const An = cur ? A0 : A1;

            // Issue next tile's gather first: its load latency hides under
            // other warps' mma (no barrier in between).
            if (j + 1 < segEnd)
                gather_tile(An, feats, imk, (j + 1 - kt0) << 7, Mtot, tid);

            // MMA: 32x32 warp tile = 2(M) x 4(N) frags, 16 K-steps.
            float acc[2][4][4];
#pragma unroll
            for (int mt = 0; mt < 2; ++mt)
#pragma unroll
                for (int nt = 0; nt < 4; ++nt)
#pragma unroll
                    for (int e = 0; e < 4; ++e) acc[mt][nt][e] = 0.f;

#pragma unroll 4
            for (int ks = 0; ks < 16; ++ks) {
                const int kb = ks << 3;
                uint32_t a[2][4];
#pragma unroll
                for (int mt = 0; mt < 2; ++mt) {
                    const int r = (warp_m << 5) + (mt << 4) + gid;
                    a[mt][0] = __float_as_uint(Ac[r * SAF + kb + tg]);
                    a[mt][1] = __float_as_uint(Ac[(r + 8) * SAF + kb + tg]);
                    a[mt][2] = __float_as_uint(Ac[r * SAF + kb + tg + 4]);
                    a[mt][3] = __float_as_uint(Ac[(r + 8) * SAF + kb + tg + 4]);
                }
#pragma unroll
                for (int nt = 0; nt < 4; ++nt) {
                    const int cn = (warp_n << 5) + (nt << 3) + gid;
                    uint32_t b0 = __float_as_uint(Bs[(kb + tg) * SBF + cn]);
                    uint32_t b1 = __float_as_uint(Bs[(kb + tg + 4) * SBF + cn]);
                    mma8(acc[0][nt], a[0], b0, b1);
                    mma8(acc[1][nt], a[1], b0, b1);
                }
            }
            __syncthreads();   // mma done reading Ac; gather into An complete

            // Bounce C fragments into Ac.
#pragma unroll
            for (int mt = 0; mt < 2; ++mt)
#pragma unroll
                for (int nt = 0; nt < 4; ++nt) {
                    const int r = (warp_m << 5) + (mt << 4) + gid;
                    const int c = (warp_n << 5) + (nt << 3) + (tg << 1);
                    *reinterpret_cast<float2*>(&Ac[r * SAF + c]) =
                        make_float2(acc[mt][nt][0], acc[mt][nt][1]);
                    *reinterpret_cast<float2*>(&Ac[(r + 8) * SAF + c]) =
                        make_float2(acc[mt][nt][2], acc[mt][nt][3]);
                }
            __syncthreads();

            // Scatter: warp w -> rows w*8 + (l&7) (8 distinct rows per LDS
            // phase => bank-conflict-free), col block (l>>3)*32.
            {
                const int r  = (wid << 3) + (lane & 7);
                const int cb = (lane >> 3) << 5;
                const int gm = tb + r;
                if (gm < Mtot) {
                    float* optr = out + (size_t)__ldg(omk + gm) * CCH + cb;
                    const float* crow = &Ac[r * SAF + cb];
#pragma unroll
                    for (int q = 0; q < 8; ++q) {
                        float4 v = *reinterpret_cast<const float4*>(crow + (q << 2));
                        asm volatile("red.global.add.v4.f32 [%0], {%1,%2,%3,%4};" ::
                                     "l"(optr + (q << 2)),
                                     "f"(v.x), "f"(v.y), "f"(v.z), "f"(v.w) : "memory");
                    }
                }
            }
            __syncthreads();   // scatter done reading Ac before it is re-gathered
            cur ^= 1;
        }
        t = segEnd;
    }
}

__global__ void __launch_bounds__(256) zero_kernel(float4* __restrict__ o, int n4) {
    int i = blockIdx.x * blockDim.x + threadIdx.x;
    if (blockIdx.x == 0 && threadIdx.x < CCH) { g_sum[threadIdx.x] = 0.f; g_sqs[threadIdx.x] = 0.f; }
    for (; i < n4; i += gridDim.x * blockDim.x)
        o[i] = make_float4(0.f, 0.f, 0.f, 0.f);
}

__global__ void __launch_bounds__(256) stats_kernel(const float4* __restrict__ out4, int Nrows) {
    __shared__ float4 ss[256], sq[256];
    const int tid = threadIdx.x, c4 = tid & 31, rl = tid >> 5;
    float4 s = make_float4(0.f, 0.f, 0.f, 0.f), q = s;
    for (int r = blockIdx.x * 8 + rl; r < Nrows; r += gridDim.x * 8) {
        float4 v = __ldg(out4 + (size_t)r * 32 + c4);
        s.x += v.x; s.y += v.y; s.z += v.z; s.w += v.w;
        q.x += v.x * v.x; q.y += v.y * v.y; q.z += v.z * v.z; q.w += v.w * v.w;
    }
    ss[tid] = s; sq[tid] = q;
    __syncthreads();
    if (rl == 0) {
#pragma unroll
        for (int j = 1; j < 8; ++j) {
            float4 a = ss[c4 + (j << 5)], b = sq[c4 + (j << 5)];
            s.x += a.x; s.y += a.y; s.z += a.z; s.w += a.w;
            q.x += b.x; q.y += b.y; q.z += b.z; q.w += b.w;
        }
        const int c = c4 << 2;
        atomicAdd(&g_sum[c + 0], s.x); atomicAdd(&g_sum[c + 1], s.y);
        atomicAdd(&g_sum[c + 2], s.z); atomicAdd(&g_sum[c + 3], s.w);
        atomicAdd(&g_sqs[c + 0], q.x); atomicAdd(&g_sqs[c + 1], q.y);
        atomicAdd(&g_sqs[c + 2], q.z); atomicAdd(&g_sqs[c + 3], q.w);
    }
}

__global__ void __launch_bounds__(256) norm_kernel(float4* __restrict__ out4,
                                                   const float* __restrict__ gamma,
                                                   const float* __restrict__ beta, int Nrows) {
    const int tid = threadIdx.x, c4 = tid & 31, rl = tid >> 5;
    const float invN = 1.0f / (float)Nrows;
    const int c = c4 << 2;
    float4 A, B;
    {
        float m0 = g_sum[c + 0] * invN, m1 = g_sum[c + 1] * invN;
        float m2 = g_sum[c + 2] * invN, m3 = g_sum[c + 3] * invN;
        A.x = rsqrtf(fmaxf(g_sqs[c + 0] * invN - m0 * m0, 0.f) + 1e-5f) * __ldg(gamma + c + 0);
        A.y = rsqrtf(fmaxf(g_sqs[c + 1] * invN - m1 * m1, 0.f) + 1e-5f) * __ldg(gamma + c + 1);
        A.z = rsqrtf(fmaxf(g_sqs[c + 2] * invN - m2 * m2, 0.f) + 1e-5f) * __ldg(gamma + c + 2);
        A.w = rsqrtf(fmaxf(g_sqs[c + 3] * invN - m3 * m3, 0.f) + 1e-5f) * __ldg(gamma + c + 3);
        B.x = __ldg(beta + c + 0) - m0 * A.x;
        B.y = __ldg(beta + c + 1) - m1 * A.y;
        B.z = __ldg(beta + c + 2) - m2 * A.z;
        B.w = __ldg(beta + c + 3) - m3 * A.w;
    }
    for (int r = blockIdx.x * 8 + rl; r < Nrows; r += gridDim.x * 8) {
        const size_t idx = (size_t)r * 32 + c4;
        float4 v = out4[idx];
        v.x = fmaf(v.x, A.x, B.x); v.y = fmaf(v.y, A.y, B.y);
        v.z = fmaf(v.z, A.z, B.z); v.w = fmaf(v.w, A.w, B.w);
        out4[idx] = v;
    }
}

extern "C" void kernel_launch(void* const* d_in, const int* in_sizes, int n_in,
                              void* d_out, int out_size) {
    const float* feats    = (const float*)d_in[0];
    const float* Wmat     = (const float*)d_in[1];
    const float* gamma    = (const float*)d_in[2];
    const float* beta     = (const float*)d_in[3];
    const int*   in_maps  = (const int*)d_in[4];
    const int*   out_maps = (const int*)d_in[5];
    float* out = (float*)d_out;

    const int Mtot  = in_sizes[4] / KK3;
    const int Nrows = out_size / CCH;

    cudaFuncSetAttribute(conv_kernel, cudaFuncAttributeMaxDynamicSharedMemorySize, SMEM_DYN);

    zero_kernel<<<2048, 256>>>((float4*)out, Nrows * (CCH / 4));
    conv_kernel<<<152, 512, SMEM_DYN>>>(feats, Wmat, in_maps, out_maps, out, Mtot);
    stats_kernel<<<1024, 256>>>((const float4*)out, Nrows);
    norm_kernel<<<1024, 256>>>((float4*)out, gamma, beta, Nrows);
}

// round 12
// speedup vs baseline: 1.9158x; 1.1929x over previous
#include <cuda_runtime.h>
#include <cstdint>

#define CCH 128
#define KK3 27
#define SAF 132                         // A smem row stride (floats) — conflict-free A frags
#define SBF 136                         // B smem row stride (floats) — conflict-free B frags
#define SMEM_DYN (2 * 128 * SAF * 4 + 128 * SBF * 4)   // 204800 B -> 1 CTA/SM

__device__ float g_sum[CCH];
__device__ float g_sqs[CCH];

static __device__ __forceinline__ float to_tf32(float x) {
    float r; asm("cvt.rna.tf32.f32 %0, %1;" : "=f"(r) : "f"(x)); return r;
}

static __device__ __forceinline__ void mma8(float* c, const uint32_t* a,
                                            uint32_t b0, uint32_t b1) {
    asm volatile(
        "mma.sync.aligned.m16n8k8.row.col.f32.tf32.tf32.f32 "
        "{%0,%1,%2,%3}, {%4,%5,%6,%7}, {%8,%9}, {%0,%1,%2,%3};"
        : "+f"(c[0]), "+f"(c[1]), "+f"(c[2]), "+f"(c[3])
        : "r"(a[0]), "r"(a[1]), "r"(a[2]), "r"(a[3]), "r"(b0), "r"(b1));
}

// Gather 128x128 f32 tile into smem (stride SAF). One warp = one row per step
// (idx broadcast, 512B coalesced row read). OOB rows -> 0. tf32-rounded.
static __device__ __forceinline__ void gather_tile(float* __restrict__ As,
                                                   const float* __restrict__ feats,
                                                   const int* __restrict__ imk,
                                                   int tb, int Mtot, int tid) {
#pragma unroll
    for (int p = 0; p < 8; ++p) {
        int lin = (p << 9) + tid;
        int row = lin >> 5, q = lin & 31;
        int gm  = tb + row;
        float4 v = make_float4(0.f, 0.f, 0.f, 0.f);
        if (gm < Mtot) {
            int g = __ldg(imk + gm);
            v = __ldg(reinterpret_cast<const float4*>(feats) + ((size_t)g << 5) + q);
            v.x = to_tf32(v.x); v.y = to_tf32(v.y);
            v.z = to_tf32(v.z); v.w = to_tf32(v.w);
        }
        *reinterpret_cast<float4*>(&As[row * SAF + (q << 2)]) = v;
    }
}

// ---------------------------------------------------------------------------
// Persistent conv. Per tile (ONE CTA barrier):
//   gather(next)->An  ||  mma(Ac)  ||  shfl-transpose frags -> red.global.v4
// 512 thr, 16 warps 4x4, 32x32 warp tiles, A double-buffered, B per k-segment.
// ---------------------------------------------------------------------------
__global__ void __launch_bounds__(512, 1)
conv_kernel(const float* __restrict__ feats, const float* __restrict__ Wmat,
            const int* __restrict__ in_maps, const int* __restrict__ out_maps,
            float* __restrict__ out, int Mtot) {
    extern __shared__ float sm[];
    float* const A0 = sm;
    float* const A1 = sm + 128 * SAF;
    float* const Bs = sm + 2 * 128 * SAF;

    const int tid  = threadIdx.x;
    const int wid  = tid >> 5;
    const int lane = tid & 31;
    const int gid  = lane >> 2;      // 0..7
    const int tg   = lane & 3;       // 0..3
    const int warp_m = wid & 3;
    const int warp_n = wid >> 2;
    const bool odd = (tg & 1);

    const int TPK   = (Mtot + 127) >> 7;
    const int total = KK3 * TPK;
    const int chunk = (total + gridDim.x - 1) / gridDim.x;
    int t = blockIdx.x * chunk;
    const int t1 = min(total, t + chunk);

    while (t < t1) {
        const int kk     = t / TPK;
        const int segEnd = min(t1, (kk + 1) * TPK);
        const int kt0    = kk * TPK;
        const int* imk   = in_maps  + (size_t)kk * Mtot;
        const int* omk   = out_maps + (size_t)kk * Mtot;
        const float4* Wk4 = reinterpret_cast<const float4*>(Wmat + (size_t)kk * (CCH * CCH));

        // B = W[k] as [k][n], stride SBF.
#pragma unroll
        for (int p = 0; p < 8; ++p) {
            int lin4 = (p << 9) + tid;
            int row  = lin4 >> 5, n4 = lin4 & 31;
            float4 v = __ldg(Wk4 + lin4);
            v.x = to_tf32(v.x); v.y = to_tf32(v.y);
            v.z = to_tf32(v.z); v.w = to_tf32(v.w);
            *reinterpret_cast<float4*>(&Bs[row * SBF + (n4 << 2)]) = v;
        }
        gather_tile(A0, feats, imk, (t - kt0) << 7, Mtot, tid);
        __syncthreads();

        int cur = 0;
        for (int j = t; j < segEnd; ++j) {
            const int tb = (j - kt0) << 7;
            float* const Ac = cur ? A1 : A0;
            float* const An = cur ? A0 : A1;

            // Next tile's gather first: load latency hides under mma/scatter.
            if (j + 1 < segEnd)
                gather_tile(An, feats, imk, (j + 1 - kt0) << 7, Mtot, tid);

            // MMA: 32x32 warp tile = 2(M) x 4(N) frags, 16 K-steps.
            float acc[2][4][4];
#pragma unroll
            for (int mt = 0; mt < 2; ++mt)
#pragma unroll
                for (int nt = 0; nt < 4; ++nt)
#pragma unroll
                    for (int e = 0; e < 4; ++e) acc[mt][nt][e] = 0.f;

#pragma unroll 4
            for (int ks = 0; ks < 16; ++ks) {
                const int kb = ks << 3;
                uint32_t a[2][4];
#pragma unroll
                for (int mt = 0; mt < 2; ++mt) {
                    const int r = (warp_m << 5) + (mt << 4) + gid;
                    a[mt][0] = __float_as_uint(Ac[r * SAF + kb + tg]);
                    a[mt][1] = __float_as_uint(Ac[(r + 8) * SAF + kb + tg]);
                    a[mt][2] = __float_as_uint(Ac[r * SAF + kb + tg + 4]);
                    a[mt][3] = __float_as_uint(Ac[(r + 8) * SAF + kb + tg + 4]);
                }
#pragma unroll
                for (int nt = 0; nt < 4; ++nt) {
                    const int cn = (warp_n << 5) + (nt << 3) + gid;
                    uint32_t b0 = __float_as_uint(Bs[(kb + tg) * SBF + cn]);
                    uint32_t b1 = __float_as_uint(Bs[(kb + tg + 4) * SBF + cn]);
                    mma8(acc[0][nt], a[0], b0, b1);
                    mma8(acc[1][nt], a[1], b0, b1);
                }
            }

            // Scatter straight from fragments.
            // Quad lanes tg=0..3 (fixed gid) hold one row's 8 consecutive cols
            // as c0,c1 (row r) / c2,c3 (row r+8). Butterfly xor=1 with parity-
            // selected operands: even lanes assemble float4 of row r (cols
            // +{0,4}[tg&2]), odd lanes of row r+8. Then red.global.add.v4.
#pragma unroll
            for (int mt = 0; mt < 2; ++mt) {
                const int r  = (warp_m << 5) + (mt << 4) + gid + ((tg & 1) << 3);
                const int gm = tb + r;
                float* optr = nullptr;
                if (gm < Mtot)
                    optr = out + (size_t)__ldg(omk + gm) * CCH
                         + (warp_n << 5) + ((tg & 2) << 1);
#pragma unroll
                for (int nt = 0; nt < 4; ++nt) {
                    float s0 = odd ? acc[mt][nt][0] : acc[mt][nt][2];
                    float s1 = odd ? acc[mt][nt][1] : acc[mt][nt][3];
                    float p0 = __shfl_xor_sync(0xFFFFFFFFu, s0, 1);
                    float p1 = __shfl_xor_sync(0xFFFFFFFFu, s1, 1);
                    float4 v = odd
                        ? make_float4(p0, p1, acc[mt][nt][2], acc[mt][nt][3])
                        : make_float4(acc[mt][nt][0], acc[mt][nt][1], p0, p1);
                    if (optr)
                        asm volatile("red.global.add.v4.f32 [%0], {%1,%2,%3,%4};" ::
                                     "l"(optr + (nt << 3)),
                                     "f"(v.x), "f"(v.y), "f"(v.z), "f"(v.w) : "memory");
                }
            }

            __syncthreads();   // An gather complete; Ac free for next gather
            cur ^= 1;
        }
        t = segEnd;
    }
}

__global__ void __launch_bounds__(256) zero_kernel(float4* __restrict__ o, int n4) {
    int i = blockIdx.x * blockDim.x + threadIdx.x;
    if (blockIdx.x == 0 && threadIdx.x < CCH) { g_sum[threadIdx.x] = 0.f; g_sqs[threadIdx.x] = 0.f; }
    for (; i < n4; i += gridDim.x * blockDim.x)
        o[i] = make_float4(0.f, 0.f, 0.f, 0.f);
}

__global__ void __launch_bounds__(256) stats_kernel(const float4* __restrict__ out4, int Nrows) {
    __shared__ float4 ss[256], sq[256];
    const int tid = threadIdx.x, c4 = tid & 31, rl = tid >> 5;
    float4 s = make_float4(0.f, 0.f, 0.f, 0.f), q = s;
    for (int r = blockIdx.x * 8 + rl; r < Nrows; r += gridDim.x * 8) {
        float4 v = __ldg(out4 + (size_t)r * 32 + c4);
        s.x += v.x; s.y += v.y; s.z += v.z; s.w += v.w;
        q.x += v.x * v.x; q.y += v.y * v.y; q.z += v.z * v.z; q.w += v.w * v.w;
    }
    ss[tid] = s; sq[tid] = q;
    __syncthreads();
    if (rl == 0) {
#pragma unroll
        for (int j = 1; j < 8; ++j) {
            float4 a = ss[c4 + (j << 5)], b = sq[c4 + (j << 5)];
            s.x += a.x; s.y += a.y; s.z += a.z; s.w += a.w;
            q.x += b.x; q.y += b.y; q.z += b.z; q.w += b.w;
        }
        const int c = c4 << 2;
        atomicAdd(&g_sum[c + 0], s.x); atomicAdd(&g_sum[c + 1], s.y);
        atomicAdd(&g_sum[c + 2], s.z); atomicAdd(&g_sum[c + 3], s.w);
        atomicAdd(&g_sqs[c + 0], q.x); atomicAdd(&g_sqs[c + 1], q.y);
        atomicAdd(&g_sqs[c + 2], q.z); atomicAdd(&g_sqs[c + 3], q.w);
    }
}

__global__ void __launch_bounds__(256) norm_kernel(float4* __restrict__ out4,
                                                   const float* __restrict__ gamma,
                                                   const float* __restrict__ beta, int Nrows) {
    const int tid = threadIdx.x, c4 = tid & 31, rl = tid >> 5;
    const float invN = 1.0f / (float)Nrows;
    const int c = c4 << 2;
    float4 A, B;
    {
        float m0 = g_sum[c + 0] * invN, m1 = g_sum[c + 1] * invN;
        float m2 = g_sum[c + 2] * invN, m3 = g_sum[c + 3] * invN;
        A.x = rsqrtf(fmaxf(g_sqs[c + 0] * invN - m0 * m0, 0.f) + 1e-5f) * __ldg(gamma + c + 0);
        A.y = rsqrtf(fmaxf(g_sqs[c + 1] * invN - m1 * m1, 0.f) + 1e-5f) * __ldg(gamma + c + 1);
        A.z = rsqrtf(fmaxf(g_sqs[c + 2] * invN - m2 * m2, 0.f) + 1e-5f) * __ldg(gamma + c + 2);
        A.w = rsqrtf(fmaxf(g_sqs[c + 3] * invN - m3 * m3, 0.f) + 1e-5f) * __ldg(gamma + c + 3);
        B.x = __ldg(beta + c + 0) - m0 * A.x;
        B.y = __ldg(beta + c + 1) - m1 * A.y;
        B.z = __ldg(beta + c + 2) - m2 * A.z;
        B.w = __ldg(beta + c + 3) - m3 * A.w;
    }
    for (int r = blockIdx.x * 8 + rl; r < Nrows; r += gridDim.x * 8) {
        const size_t idx = (size_t)r * 32 + c4;
        float4 v = out4[idx];
        v.x = fmaf(v.x, A.x, B.x); v.y = fmaf(v.y, A.y, B.y);
        v.z = fmaf(v.z, A.z, B.z); v.w = fmaf(v.w, A.w, B.w);
        out4[idx] = v;
    }
}

extern "C" void kernel_launch(void* const* d_in, const int* in_sizes, int n_in,
                              void* d_out, int out_size) {
    const float* feats    = (const float*)d_in[0];
    const float* Wmat     = (const float*)d_in[1];
    const float* gamma    = (const float*)d_in[2];
    const float* beta     = (const float*)d_in[3];
    const int*   in_maps  = (const int*)d_in[4];
    const int*   out_maps = (const int*)d_in[5];
    float* out = (float*)d_out;

    const int Mtot  = in_sizes[4] / KK3;
    const int Nrows = out_size / CCH;

    cudaFuncSetAttribute(conv_kernel, cudaFuncAttributeMaxDynamicSharedMemorySize, SMEM_DYN);

    zero_kernel<<<2048, 256>>>((float4*)out, Nrows * (CCH / 4));
    conv_kernel<<<152, 512, SMEM_DYN>>>(feats, Wmat, in_maps, out_maps, out, Mtot);
    stats_kernel<<<1024, 256>>>((const float4*)out, Nrows);
    norm_kernel<<<1024, 256>>>((float4*)out, gamma, beta, Nrows);
}